// round 14
// baseline (speedup 1.0000x reference)
#include <cuda_runtime.h>

// Problem shape (fixed by the dataset)
#define NXK 4096
#define NC  128
#define NC4 (NC / 4)
#define NQK 262144
#define NBUCK 8192        // search-LUT bucket width 0.5 (power-of-2 scale, exact fp)
#define NSUB 8            // sub-bins per interval (atomic-contention spreading)
#define NBIN (NXK * NSUB) // 32768 scatter bins
#define SPLIT 2           // warps per interval in eval

// Scratch (no allocations allowed -> __device__ globals)
__device__ int   g_lut[NBUCK + 1];      // bucket -> count(x <= 0.5*b)
__device__ float g_coef[NXK * 4 * NC];  // [interval][plane 0..3][128 ch], 8 MB
__device__ int   g_hist[NBIN];          // per-sub-bin counts
__device__ int   g_start[NBIN + 1];     // exclusive scan
__device__ int   g_cursor[NBIN];        // scatter cursors
__device__ int   g_key[NQK];            // per-query bin key
__device__ float g_t[NQK];              // per-query t
__device__ int2  g_sorted[NQK];         // {qid, bits(t)} grouped by bin

// ---------------------------------------------------------------------------
// K1: search LUT by scatter (no dependent chains) + zero the histogram.
// lut[b] = #{ j : x[j] <= 0.5*b }.  All bucket math exact in fp32.
// ---------------------------------------------------------------------------
__global__ __launch_bounds__(256) void lut_kernel(const float* __restrict__ x) {
    int j = blockIdx.x * 256 + threadIdx.x;
    if (j >= NXK) return;
#pragma unroll
    for (int s = 0; s < NSUB; ++s) g_hist[j * NSUB + s] = 0;

    float xj = __ldg(x + j);
    if (j == 0) {
        for (int b = 0; 0.5f * (float)b < xj && b <= NBUCK; ++b) g_lut[b] = 0;
    }
    int b = (int)ceilf(2.0f * xj);
    if (b < 0) b = 0;
    if (j == NXK - 1) {
        for (; b <= NBUCK; ++b) g_lut[b] = NXK;
    } else {
        float xn = __ldg(x + j + 1);
        for (; b <= NBUCK && 0.5f * (float)b < xn; ++b) g_lut[b] = j + 1;
    }
}

// ---------------------------------------------------------------------------
// K2: per-interval Horner coefficients, fp32, plane layout.
// fq = b0 + t*(b1 + t*(b2 + t*b3)); math identical to reference.
// ---------------------------------------------------------------------------
__global__ __launch_bounds__(256) void coef_kernel(const float* __restrict__ x,
                                                   const float* __restrict__ f) {
    int gid = blockIdx.x * 256 + threadIdx.x;
    int i   = gid >> 7;          // interval
    int c   = gid & 127;         // channel
    if (i < 1 || i >= NXK) return;

    float x0  = __ldg(x + i - 1);
    float x1  = __ldg(x + i);
    float dx  = x1 - x0;
    float dxi = (dx == 0.f) ? 0.f : 1.f / dx;

    float f0 = __ldg(f + (i - 1) * NC + c);
    float f1 = __ldg(f + i * NC + c);
    float dfc = (f1 - f0) * dxi;

    float fx0, fx1;
    if (i == 1) {
        fx0 = dfc;
    } else {
        float xm   = __ldg(x + i - 2);
        float dxm  = x0 - xm;
        float dxim = (dxm == 0.f) ? 0.f : 1.f / dxm;
        float fm   = __ldg(f + (i - 2) * NC + c);
        fx0 = 0.5f * ((f0 - fm) * dxim + dfc);
    }
    if (i == NXK - 1) {
        fx1 = dfc;
    } else {
        float xp   = __ldg(x + i + 1);
        float dxp  = xp - x1;
        float dxip = (dxp == 0.f) ? 0.f : 1.f / dxp;
        float fp   = __ldg(f + (i + 1) * NC + c);
        fx1 = 0.5f * (dfc + (fp - f1) * dxip);
    }

    float d0 = fx0 * dx;
    float d1 = fx1 * dx;
    float c2 = -3.f * f0 + 3.f * f1 - 2.f * d0 - d1;
    float c3 =  2.f * f0 - 2.f * f1 + d0 + d1;

    float* base = g_coef + i * (4 * NC) + c;
    base[0 * NC] = f0;
    base[1 * NC] = d0;
    base[2 * NC] = c2;
    base[3 * NC] = c3;
}

// ---------------------------------------------------------------------------
// K3: index pass.  Thread per query: search via LUT, compute t, histogram.
// Bin key spreads each interval over NSUB sub-bins keyed by q>>15, cutting
// per-address atomic contention from ~64 to ~8.
// ---------------------------------------------------------------------------
__global__ __launch_bounds__(256) void index_kernel(const float* __restrict__ xq,
                                                    const float* __restrict__ x) {
    int q = blockIdx.x * 256 + threadIdx.x;
    if (q >= NQK) return;
    float v = __ldg(xq + q);

    int b = (int)(v * 2.0f);
    b = (b < 0) ? 0 : ((b > NBUCK - 1) ? NBUCK - 1 : b);
    int i  = __ldg(g_lut + b);
    int hi = __ldg(g_lut + b + 1);
    while (i < hi && __ldg(x + i) <= v) ++i;   // searchsorted side='right'
    i = (i < 1) ? 1 : ((i > NXK - 1) ? NXK - 1 : i);

    float x0  = __ldg(x + i - 1);
    float x1  = __ldg(x + i);
    float dx  = x1 - x0;
    float dxi = (dx == 0.f) ? 0.f : 1.f / dx;
    float t   = (v - x0) * dxi;

    int key = i * NSUB + (q >> 15);            // q/32768 in 0..7
    g_key[q] = key;
    g_t[q]   = t;
    atomicAdd(&g_hist[key], 1);
}

// ---------------------------------------------------------------------------
// K4: single-block exclusive scan of 32768 bins (1024 thr x 32 bins each).
// ---------------------------------------------------------------------------
__global__ __launch_bounds__(1024) void scan_kernel() {
    __shared__ int s[1024];
    int t = threadIdx.x;
    int base = t * 32;
    const int4* hp = (const int4*)(g_hist) + t * 8;
    int h[32], sum = 0;
#pragma unroll
    for (int k = 0; k < 8; ++k) {
        int4 v = hp[k];
        h[4 * k] = v.x; h[4 * k + 1] = v.y; h[4 * k + 2] = v.z; h[4 * k + 3] = v.w;
        sum += v.x + v.y + v.z + v.w;
    }
    s[t] = sum;
    __syncthreads();
#pragma unroll
    for (int off = 1; off < 1024; off <<= 1) {
        int v = (t >= off) ? s[t - off] : 0;
        __syncthreads();
        s[t] += v;
        __syncthreads();
    }
    int run = s[t] - sum;                      // exclusive prefix of this chunk
#pragma unroll
    for (int k = 0; k < 32; ++k) {
        g_start[base + k]  = run;
        g_cursor[base + k] = run;
        run += h[k];
    }
    if (t == 1023) g_start[NBIN] = run;
}

// ---------------------------------------------------------------------------
// K5: scatter {qid, t} into bin-grouped order (order within bin is
// nondeterministic but every query is written exactly once with the same
// value -> output deterministic).
// ---------------------------------------------------------------------------
__global__ __launch_bounds__(256) void scatter_kernel() {
    int q = blockIdx.x * 256 + threadIdx.x;
    if (q >= NQK) return;
    int key = __ldg(g_key + q);
    float tv = __ldg(g_t + q);
    int pos = atomicAdd(&g_cursor[key], 1);
    g_sorted[pos] = make_int2(q, __float_as_int(tv));
}

// ---------------------------------------------------------------------------
// K6: eval.  SPLIT warps per interval; coef planes loaded ONCE per warp into
// registers, then each query costs 1 uniform 8B load + 12 FMA + 512B store.
// Sub-bins of one interval are contiguous in g_sorted, so the warp's range is
// [start[i*NSUB], start[(i+1)*NSUB]).
// ---------------------------------------------------------------------------
__global__ __launch_bounds__(256) void eval_kernel(float* __restrict__ out) {
    int gw   = blockIdx.x * 8 + (threadIdx.x >> 5);
    int lane = threadIdx.x & 31;
    int i    = gw >> 1;            // interval (SPLIT=2)
    int half = gw & 1;
    if (i < 1 || i >= NXK) return;

    int jbeg = __ldg(&g_start[i * NSUB]) + half;
    int jend = __ldg(&g_start[(i + 1) * NSUB]);
    if (jbeg >= jend) return;

    const float4* p = (const float4*)(g_coef + i * (4 * NC));
    float4 b0 = __ldg(p + lane);
    float4 b1 = __ldg(p + NC4 + lane);
    float4 b2 = __ldg(p + 2 * NC4 + lane);
    float4 b3 = __ldg(p + 3 * NC4 + lane);

    float4* out4 = (float4*)out;
    for (int j = jbeg; j < jend; j += SPLIT) {
        int2  s = __ldg(g_sorted + j);
        float t = __int_as_float(s.y);
        float4 o;
        o.x = fmaf(t, fmaf(t, fmaf(t, b3.x, b2.x), b1.x), b0.x);
        o.y = fmaf(t, fmaf(t, fmaf(t, b3.y, b2.y), b1.y), b0.y);
        o.z = fmaf(t, fmaf(t, fmaf(t, b3.z, b2.z), b1.z), b0.z);
        o.w = fmaf(t, fmaf(t, fmaf(t, b3.w, b2.w), b1.w), b0.w);
        __stcs(out4 + s.x * NC4 + lane, o);
    }
}

extern "C" void kernel_launch(void* const* d_in, const int* in_sizes, int n_in,
                              void* d_out, int out_size) {
    const float* xq = (const float*)d_in[0];   // [NQ]
    const float* x  = (const float*)d_in[1];   // [NX]
    const float* f  = (const float*)d_in[2];   // [NX, C]
    float* out      = (float*)d_out;           // [NQ, C]

    (void)in_sizes; (void)n_in; (void)out_size;

    lut_kernel<<<NXK / 256, 256>>>(x);
    coef_kernel<<<(NXK * NC) / 256, 256>>>(x, f);
    index_kernel<<<NQK / 256, 256>>>(xq, x);
    scan_kernel<<<1, 1024>>>();
    scatter_kernel<<<NQK / 256, 256>>>();
    eval_kernel<<<(NXK * SPLIT) / 8, 256>>>(out);
}

// round 16
// speedup vs baseline: 1.6037x; 1.6037x over previous
#include <cuda_runtime.h>

// Problem shape (fixed by the dataset)
#define NXK 4096
#define NC  128
#define NC4 (NC / 4)
#define NQK 262144
#define NBUCK 8192        // search-LUT bucket width 0.5 (power-of-2 scale, exact fp)
#define NSUB 8            // sub-bins per interval (atomic-contention spreading)
#define NBIN (NXK * NSUB) // 32768 scatter bins
#define SPLIT 4           // warps per interval in eval
#define NCHUNK 128        // scan chunks (256 bins each)

// Scratch (no allocations allowed -> __device__ globals)
__device__ int   g_lut[NBUCK + 1];      // bucket -> count(x <= 0.5*b)
__device__ float g_coef[NXK * 4 * NC];  // [interval][plane 0..3][128 ch], 8 MB
__device__ int   g_hist[NBIN];          // per-sub-bin counts
__device__ int   g_partial[NCHUNK];     // per-chunk sums
__device__ int   g_start[NBIN + 1];     // exclusive scan
__device__ int   g_cursor[NBIN];        // scatter cursors
__device__ int   g_key[NQK];            // per-query bin key
__device__ float g_t[NQK];              // per-query t
__device__ int2  g_sorted[NQK];         // {qid, bits(t)} grouped by bin

// ---------------------------------------------------------------------------
// K1 (fused): blocks [0, 2048) -> Horner coefficients (plane layout);
//             blocks [2048, 2064) -> search LUT by scatter + histogram zero.
// ---------------------------------------------------------------------------
#define COEF_BLOCKS ((NXK * NC) / 256)   // 2048
__global__ __launch_bounds__(256) void prep_kernel(const float* __restrict__ x,
                                                   const float* __restrict__ f) {
    if (blockIdx.x < COEF_BLOCKS) {
        int gid = blockIdx.x * 256 + threadIdx.x;
        int i   = gid >> 7;          // interval
        int c   = gid & 127;         // channel
        if (i < 1 || i >= NXK) return;

        float x0  = __ldg(x + i - 1);
        float x1  = __ldg(x + i);
        float dx  = x1 - x0;
        float dxi = (dx == 0.f) ? 0.f : 1.f / dx;

        float f0 = __ldg(f + (i - 1) * NC + c);
        float f1 = __ldg(f + i * NC + c);
        float dfc = (f1 - f0) * dxi;

        float fx0, fx1;
        if (i == 1) {
            fx0 = dfc;
        } else {
            float xm   = __ldg(x + i - 2);
            float dxm  = x0 - xm;
            float dxim = (dxm == 0.f) ? 0.f : 1.f / dxm;
            float fm   = __ldg(f + (i - 2) * NC + c);
            fx0 = 0.5f * ((f0 - fm) * dxim + dfc);
        }
        if (i == NXK - 1) {
            fx1 = dfc;
        } else {
            float xp   = __ldg(x + i + 1);
            float dxp  = xp - x1;
            float dxip = (dxp == 0.f) ? 0.f : 1.f / dxp;
            float fp   = __ldg(f + (i + 1) * NC + c);
            fx1 = 0.5f * (dfc + (fp - f1) * dxip);
        }

        float d0 = fx0 * dx;
        float d1 = fx1 * dx;
        float c2 = -3.f * f0 + 3.f * f1 - 2.f * d0 - d1;
        float c3 =  2.f * f0 - 2.f * f1 + d0 + d1;

        float* base = g_coef + i * (4 * NC) + c;
        base[0 * NC] = f0;
        base[1 * NC] = d0;
        base[2 * NC] = c2;
        base[3 * NC] = c3;
    } else {
        int j = (blockIdx.x - COEF_BLOCKS) * 256 + threadIdx.x;
        if (j >= NXK) return;
#pragma unroll
        for (int s = 0; s < NSUB; ++s) g_hist[j * NSUB + s] = 0;

        float xj = __ldg(x + j);
        if (j == 0) {
            for (int b = 0; 0.5f * (float)b < xj && b <= NBUCK; ++b) g_lut[b] = 0;
        }
        int b = (int)ceilf(2.0f * xj);
        if (b < 0) b = 0;
        if (j == NXK - 1) {
            for (; b <= NBUCK; ++b) g_lut[b] = NXK;
        } else {
            float xn = __ldg(x + j + 1);
            for (; b <= NBUCK && 0.5f * (float)b < xn; ++b) g_lut[b] = j + 1;
        }
    }
}

// ---------------------------------------------------------------------------
// K2: index pass.  Thread per query: search via LUT, compute t, histogram.
// ---------------------------------------------------------------------------
__global__ __launch_bounds__(256) void index_kernel(const float* __restrict__ xq,
                                                    const float* __restrict__ x) {
    int q = blockIdx.x * 256 + threadIdx.x;
    if (q >= NQK) return;
    float v = __ldg(xq + q);

    int b = (int)(v * 2.0f);
    b = (b < 0) ? 0 : ((b > NBUCK - 1) ? NBUCK - 1 : b);
    int i  = __ldg(g_lut + b);
    int hi = __ldg(g_lut + b + 1);
    while (i < hi && __ldg(x + i) <= v) ++i;   // searchsorted side='right'
    i = (i < 1) ? 1 : ((i > NXK - 1) ? NXK - 1 : i);

    float x0  = __ldg(x + i - 1);
    float x1  = __ldg(x + i);
    float dx  = x1 - x0;
    float dxi = (dx == 0.f) ? 0.f : 1.f / dx;
    float t   = (v - x0) * dxi;

    int key = i * NSUB + (q >> 15);            // q/32768 in 0..7
    g_key[q] = key;
    g_t[q]   = t;
    atomicAdd(&g_hist[key], 1);
}

// ---------------------------------------------------------------------------
// K3a: per-chunk sums.  128 blocks x 256 threads, tree reduce in smem.
// ---------------------------------------------------------------------------
__global__ __launch_bounds__(256) void scan_a_kernel() {
    __shared__ int red[256];
    int b = blockIdx.x, t = threadIdx.x;
    red[t] = g_hist[b * 256 + t];
    __syncthreads();
#pragma unroll
    for (int off = 128; off > 0; off >>= 1) {
        if (t < off) red[t] += red[t + off];
        __syncthreads();
    }
    if (t == 0) g_partial[b] = red[0];
}

// ---------------------------------------------------------------------------
// K3b: finalize.  128 blocks; every block redundantly scans the 128 partials
// (512B, trivial), then block-scans its own 256 bins and writes start/cursor.
// ---------------------------------------------------------------------------
__global__ __launch_bounds__(256) void scan_c_kernel() {
    __shared__ int part[NCHUNK];
    __shared__ int s[256];
    int b = blockIdx.x, t = threadIdx.x;

    if (t < NCHUNK) part[t] = g_partial[t];
    __syncthreads();
    // inclusive Hillis-Steele over 128 partials
#pragma unroll
    for (int off = 1; off < NCHUNK; off <<= 1) {
        int v = (t >= off && t < NCHUNK) ? part[t - off] : 0;
        __syncthreads();
        if (t < NCHUNK) part[t] += v;
        __syncthreads();
    }
    int chunk_off = (b == 0) ? 0 : part[b - 1];

    int h = g_hist[b * 256 + t];
    s[t] = h;
    __syncthreads();
#pragma unroll
    for (int off = 1; off < 256; off <<= 1) {
        int v = (t >= off) ? s[t - off] : 0;
        __syncthreads();
        s[t] += v;
        __syncthreads();
    }
    int start = chunk_off + s[t] - h;          // exclusive
    int bin = b * 256 + t;
    g_start[bin]  = start;
    g_cursor[bin] = start;
    if (bin == NBIN - 1) g_start[NBIN] = chunk_off + s[t];
}

// ---------------------------------------------------------------------------
// K4: scatter {qid, t} into bin-grouped order (within-bin order is
// nondeterministic; each output row written exactly once -> deterministic).
// ---------------------------------------------------------------------------
__global__ __launch_bounds__(256) void scatter_kernel() {
    int q = blockIdx.x * 256 + threadIdx.x;
    if (q >= NQK) return;
    int   key = __ldg(g_key + q);
    float tv  = __ldg(g_t + q);
    int pos = atomicAdd(&g_cursor[key], 1);
    g_sorted[pos] = make_int2(q, __float_as_int(tv));
}

// ---------------------------------------------------------------------------
// K5: eval.  SPLIT=4 warps per interval; coef planes register-resident.
// Inner loop: software-pipelined info prefetch hides the ~L2 latency of the
// uniform {qid,t} load behind compute+store of the current query.
// ---------------------------------------------------------------------------
__global__ __launch_bounds__(256) void eval_kernel(float* __restrict__ out) {
    int gw   = blockIdx.x * 8 + (threadIdx.x >> 5);
    int lane = threadIdx.x & 31;
    int i    = gw >> 2;            // interval (SPLIT=4)
    int part = gw & 3;
    if (i < 1 || i >= NXK) return;

    int jbeg = __ldg(&g_start[i * NSUB]) + part;
    int jend = __ldg(&g_start[(i + 1) * NSUB]);
    if (jbeg >= jend) return;

    const float4* p = (const float4*)(g_coef + i * (4 * NC));
    float4 b0 = __ldg(p + lane);
    float4 b1 = __ldg(p + NC4 + lane);
    float4 b2 = __ldg(p + 2 * NC4 + lane);
    float4 b3 = __ldg(p + 3 * NC4 + lane);

    float4* out4 = (float4*)out;
    int2 nxt = __ldg(g_sorted + jbeg);
    for (int j = jbeg; j < jend; j += SPLIT) {
        int2 s = nxt;
        int jn = j + SPLIT;
        if (jn < jend) nxt = __ldg(g_sorted + jn);

        float t = __int_as_float(s.y);
        float4 o;
        o.x = fmaf(t, fmaf(t, fmaf(t, b3.x, b2.x), b1.x), b0.x);
        o.y = fmaf(t, fmaf(t, fmaf(t, b3.y, b2.y), b1.y), b0.y);
        o.z = fmaf(t, fmaf(t, fmaf(t, b3.z, b2.z), b1.z), b0.z);
        o.w = fmaf(t, fmaf(t, fmaf(t, b3.w, b2.w), b1.w), b0.w);
        __stcs(out4 + s.x * NC4 + lane, o);
    }
}

extern "C" void kernel_launch(void* const* d_in, const int* in_sizes, int n_in,
                              void* d_out, int out_size) {
    const float* xq = (const float*)d_in[0];   // [NQ]
    const float* x  = (const float*)d_in[1];   // [NX]
    const float* f  = (const float*)d_in[2];   // [NX, C]
    float* out      = (float*)d_out;           // [NQ, C]

    (void)in_sizes; (void)n_in; (void)out_size;

    prep_kernel<<<COEF_BLOCKS + NXK / 256, 256>>>(x, f);
    index_kernel<<<NQK / 256, 256>>>(xq, x);
    scan_a_kernel<<<NCHUNK, 256>>>();
    scan_c_kernel<<<NCHUNK, 256>>>();
    scatter_kernel<<<NQK / 256, 256>>>();
    eval_kernel<<<(NXK * SPLIT) / 8, 256>>>(out);
}

// round 17
// speedup vs baseline: 2.3012x; 1.4349x over previous
#include <cuda_runtime.h>
#include <cuda_fp16.h>

// Problem shape (fixed by the dataset)
#define NXK 4096
#define NC  128
#define NC4 (NC / 4)
#define NQK 262144
#define NBUCK 8192      // bucket width 0.5; scale 2.0 is a power of two -> exact fp
#define ISTRIDE 384     // floats per interval: 128 b0 + 128 b1 + 128 half2(c2,c3)

// Scratch (no allocations allowed -> __device__ globals)
__device__ int   g_lut[NBUCK + 1];        // bucket -> count(x <= 0.5*b)
__device__ float g_coef[NXK * ISTRIDE];   // mixed-precision planes, 6 MB
__device__ int2  g_qinfo[NQK];            // {interval i, bits(t)}

// ---------------------------------------------------------------------------
// K1: bucket LUT by scatter (coalesced, no dependent chains).
// lut[b] = #{ j : x[j] <= 0.5*b }.  All bucket math exact in fp32.
// ---------------------------------------------------------------------------
__global__ __launch_bounds__(256) void lut_kernel(const float* __restrict__ x) {
    int j = blockIdx.x * 256 + threadIdx.x;
    if (j >= NXK) return;

    float xj = __ldg(x + j);
    if (j == 0) {
        for (int b = 0; 0.5f * (float)b < xj && b <= NBUCK; ++b) g_lut[b] = 0;
    }
    int b = (int)ceilf(2.0f * xj);
    if (b < 0) b = 0;
    if (j == NXK - 1) {
        for (; b <= NBUCK; ++b) g_lut[b] = NXK;
    } else {
        float xn = __ldg(x + j + 1);
        for (; b <= NBUCK && 0.5f * (float)b < xn; ++b) g_lut[b] = j + 1;
    }
}

// ---------------------------------------------------------------------------
// K2: per-interval Horner coefficients.  fq = b0 + t*(b1 + t*(c2 + t*c3)).
// b0 (=f0) and b1 (=d0) stored fp32 (dominant error terms); c2,c3 stored as
// packed half2 (they enter with weights t^2, t^3 <= 1).
// Thread per (interval, channel).
// ---------------------------------------------------------------------------
__global__ __launch_bounds__(256) void coef_kernel(const float* __restrict__ x,
                                                   const float* __restrict__ f) {
    int gid = blockIdx.x * 256 + threadIdx.x;
    int i   = gid >> 7;          // interval
    int c   = gid & 127;         // channel
    if (i < 1 || i >= NXK) return;

    float x0  = __ldg(x + i - 1);
    float x1  = __ldg(x + i);
    float dx  = x1 - x0;
    float dxi = (dx == 0.f) ? 0.f : 1.f / dx;

    float f0 = __ldg(f + (i - 1) * NC + c);
    float f1 = __ldg(f + i * NC + c);
    float dfc = (f1 - f0) * dxi;

    float fx0, fx1;
    if (i == 1) {
        fx0 = dfc;
    } else {
        float xm   = __ldg(x + i - 2);
        float dxm  = x0 - xm;
        float dxim = (dxm == 0.f) ? 0.f : 1.f / dxm;
        float fm   = __ldg(f + (i - 2) * NC + c);
        fx0 = 0.5f * ((f0 - fm) * dxim + dfc);
    }
    if (i == NXK - 1) {
        fx1 = dfc;
    } else {
        float xp   = __ldg(x + i + 1);
        float dxp  = xp - x1;
        float dxip = (dxp == 0.f) ? 0.f : 1.f / dxp;
        float fp   = __ldg(f + (i + 1) * NC + c);
        fx1 = 0.5f * (dfc + (fp - f1) * dxip);
    }

    float d0 = fx0 * dx;
    float d1 = fx1 * dx;
    float c2 = -3.f * f0 + 3.f * f1 - 2.f * d0 - d1;
    float c3 =  2.f * f0 - 2.f * f1 + d0 + d1;

    float* base = g_coef + i * ISTRIDE;
    base[c]      = f0;                              // b0 plane (fp32)
    base[NC + c] = d0;                              // b1 plane (fp32)
    __half2 h = __floats2half2_rn(c2, c3);          // (c2,c3) plane (half2)
    reinterpret_cast<__half2*>(base + 2 * NC)[c] = h;
}

// ---------------------------------------------------------------------------
// K3: index pass.  Thread per query: LUT search + t, packed into int2.
// ---------------------------------------------------------------------------
__global__ __launch_bounds__(256) void index_kernel(const float* __restrict__ xq,
                                                    const float* __restrict__ x) {
    int q = blockIdx.x * 256 + threadIdx.x;
    if (q >= NQK) return;
    float v = __ldg(xq + q);

    int b = (int)(v * 2.0f);
    b = (b < 0) ? 0 : ((b > NBUCK - 1) ? NBUCK - 1 : b);
    int i  = __ldg(g_lut + b);
    int hi = __ldg(g_lut + b + 1);
    while (i < hi && __ldg(x + i) <= v) ++i;   // searchsorted side='right'
    i = (i < 1) ? 1 : ((i > NXK - 1) ? NXK - 1 : i);

    float x0  = __ldg(x + i - 1);
    float x1  = __ldg(x + i);
    float dx  = x1 - x0;
    float dxi = (dx == 0.f) ? 0.f : 1.f / dx;
    float t   = (v - x0) * dxi;

    g_qinfo[q] = make_int2(i, __float_as_int(t));
}

// ---------------------------------------------------------------------------
// K4: eval.  Warp per FOUR queries (R11 structure).  Per query per lane:
//   b0 float4 (16B) + b1 float4 (16B) + half2x4 uint4 (16B) -> 12 wf/query
//   + 4 store wf.  3 load instructions instead of R11's 4.
// ---------------------------------------------------------------------------
#define QPW 4
__global__ __launch_bounds__(256) void eval_kernel(float* __restrict__ out) {
    int gid  = blockIdx.x * 256 + threadIdx.x;
    int w    = gid >> 5;
    int lane = gid & 31;
    int q0   = w * QPW;

    // 4 infos via two lane-uniform int4 loads (32B aligned: q0 % 4 == 0)
    const int4* ip = (const int4*)(g_qinfo + q0);
    int4 ia = __ldg(ip);
    int4 ib = __ldg(ip + 1);
    int   iv[QPW] = { ia.x, ia.z, ib.x, ib.z };
    float tv[QPW] = { __int_as_float(ia.y), __int_as_float(ia.w),
                      __int_as_float(ib.y), __int_as_float(ib.w) };

    float4 b0[QPW], b1[QPW];
    uint4  u23[QPW];
#pragma unroll
    for (int k = 0; k < QPW; ++k) {
        const float* base = g_coef + iv[k] * ISTRIDE;
        b0[k]  = __ldg((const float4*)base + lane);
        b1[k]  = __ldg((const float4*)(base + NC) + lane);
        u23[k] = __ldg((const uint4*)(base + 2 * NC) + lane);
    }

    float4* out4 = (float4*)out;
#pragma unroll
    for (int k = 0; k < QPW; ++k) {
        float t = tv[k];
        float2 p0 = __half22float2(*reinterpret_cast<__half2*>(&u23[k].x));
        float2 p1 = __half22float2(*reinterpret_cast<__half2*>(&u23[k].y));
        float2 p2 = __half22float2(*reinterpret_cast<__half2*>(&u23[k].z));
        float2 p3 = __half22float2(*reinterpret_cast<__half2*>(&u23[k].w));
        float4 o;
        o.x = fmaf(t, fmaf(t, fmaf(t, p0.y, p0.x), b1[k].x), b0[k].x);
        o.y = fmaf(t, fmaf(t, fmaf(t, p1.y, p1.x), b1[k].y), b0[k].y);
        o.z = fmaf(t, fmaf(t, fmaf(t, p2.y, p2.x), b1[k].z), b0[k].z);
        o.w = fmaf(t, fmaf(t, fmaf(t, p3.y, p3.x), b1[k].w), b0[k].w);
        __stcs(out4 + (q0 + k) * NC4 + lane, o);
    }
}

extern "C" void kernel_launch(void* const* d_in, const int* in_sizes, int n_in,
                              void* d_out, int out_size) {
    const float* xq = (const float*)d_in[0];   // [NQ]
    const float* x  = (const float*)d_in[1];   // [NX]
    const float* f  = (const float*)d_in[2];   // [NX, C]
    float* out      = (float*)d_out;           // [NQ, C]

    (void)in_sizes; (void)n_in; (void)out_size;

    lut_kernel<<<NXK / 256, 256>>>(x);
    coef_kernel<<<(NXK * NC) / 256, 256>>>(x, f);
    index_kernel<<<NQK / 256, 256>>>(xq, x);
    eval_kernel<<<(NQK / QPW) / 8, 256>>>(out);
}